// round 6
// baseline (speedup 1.0000x reference)
#include <cuda_runtime.h>

#define BB 64
#define TT 2048
#define DK 128
#define DV 128

// ---- packed f32x2 helpers (SASS FFMA2 path — PTX-only) ----
__device__ __forceinline__ unsigned long long pk2(float lo, float hi) {
    unsigned long long r;
    asm("mov.b64 %0, {%1,%2};" : "=l"(r) : "f"(lo), "f"(hi));
    return r;
}
__device__ __forceinline__ unsigned long long fma2(unsigned long long a, unsigned long long b, unsigned long long c) {
    unsigned long long d;
    asm("fma.rn.f32x2 %0, %1, %2, %3;" : "=l"(d) : "l"(a), "l"(b), "l"(c));
    return d;
}
__device__ __forceinline__ unsigned long long mul2_(unsigned long long a, unsigned long long b) {
    unsigned long long d;
    asm("mul.rn.f32x2 %0, %1, %2;" : "=l"(d) : "l"(a), "l"(b));
    return d;
}
__device__ __forceinline__ float2 up2(unsigned long long a) {
    float2 f;
    asm("mov.b64 {%0,%1}, %2;" : "=f"(f.x), "=f"(f.y) : "l"(a));
    return f;
}

struct Buf {
    unsigned long long q2[4];  // this warp's 8 q floats (k rows [8w,8w+8)), packed pairwise
    unsigned long long k2[4];  // this warp's 8 k floats
    float2 v2;                 // lane's 2 v columns
};

__global__ void __launch_bounds__(512, 1)
lmm_scan_kernel(const float* __restrict__ q,
                const float* __restrict__ k,
                const float* __restrict__ v,
                const float* __restrict__ alpha,
                const float* __restrict__ rho,
                const float* __restrict__ lam,
                const float* __restrict__ init,
                float* __restrict__ out)
{
    // CTA = (batch, v-half). 16 warps; warp w owns k rows [8w,8w+8) x 64 v cols.
    // Lane owns 8k x 2v = 8 packed regs. No shuffles, no global atomics:
    // partial sums over each warp's 8 k-rows go to smem; every 4 steps one
    // __syncthreads + 16-way add + coalesced STG (double-buffered smem).
    __shared__ float part[2][4][16][64];   // [buf][step-in-block][warp][vcol] = 32 KB

    const int bid   = blockIdx.x;
    const int b     = bid >> 1;
    const int vhalf = bid & 1;
    const int tid   = threadIdx.x;
    const int warp  = tid >> 5;
    const int lane  = tid & 31;
    const int krow  = warp * 8;                 // warp's 8 k rows
    const int vcol  = vhalf * 64 + lane * 2;    // lane's 2 v columns

    // ---- state M[krow..krow+8) x [vcol..vcol+2), packed pairwise along k ----
    unsigned long long M2[4][2];
    {
        const float* ist = init + (size_t)b * DK * DV;
        #pragma unroll
        for (int kp = 0; kp < 4; kp++) {
            const float* r0 = ist + (size_t)(krow + 2 * kp) * DV + vcol;
            const float* r1 = r0 + DV;
            M2[kp][0] = pk2(r0[0], r1[0]);
            M2[kp][1] = pk2(r0[1], r1[1]);
        }
    }

    const size_t bT = (size_t)b * TT;

    auto load = [&](Buf& bf, int t) {
        size_t roff = (bT + (size_t)t) * DK;
        // warp-uniform 32B loads (all lanes same address -> 1 line each)
        const ulonglong2* qp = reinterpret_cast<const ulonglong2*>(q + roff + krow);
        ulonglong2 x = qp[0], y = qp[1];
        bf.q2[0] = x.x; bf.q2[1] = x.y; bf.q2[2] = y.x; bf.q2[3] = y.y;
        const ulonglong2* kp_ = reinterpret_cast<const ulonglong2*>(k + roff + krow);
        x = kp_[0]; y = kp_[1];
        bf.k2[0] = x.x; bf.k2[1] = x.y; bf.k2[2] = y.x; bf.k2[3] = y.y;
        bf.v2 = *reinterpret_cast<const float2*>(v + roff + vcol);
    };

    auto step = [&](const Buf& bf, float sA, float sR, float sL, int ts, int bs) {
        float w = sA * sR;
        unsigned long long l2  = pk2(sL, sL);
        float w0 = w * bf.v2.x, w1 = w * bf.v2.y;
        unsigned long long wv0 = pk2(w0, w0);
        unsigned long long wv1 = pk2(w1, w1);
        unsigned long long racc0, racc1;
        #pragma unroll
        for (int kp = 0; kp < 4; kp++) {
            unsigned long long t0 = mul2_(bf.k2[kp], wv0);      // (w*v0)*k
            M2[kp][0] = fma2(l2, M2[kp][0], t0);                // M = l*M + wv*k
            racc0 = (kp == 0) ? mul2_(bf.q2[0], M2[0][0])       // r += q*M (post-update)
                              : fma2(bf.q2[kp], M2[kp][0], racc0);
            unsigned long long t1 = mul2_(bf.k2[kp], wv1);
            M2[kp][1] = fma2(l2, M2[kp][1], t1);
            racc1 = (kp == 0) ? mul2_(bf.q2[0], M2[0][1])
                              : fma2(bf.q2[kp], M2[kp][1], racc1);
        }
        float r0, r1;
        { float2 u = up2(racc0); r0 = u.x + u.y; }
        { float2 u = up2(racc1); r1 = u.x + u.y; }
        // partial over this warp's 8 k rows -> smem (conflict-free float2)
        *reinterpret_cast<float2*>(&part[bs][ts][warp][lane * 2]) = make_float2(r0, r1);
    };

    Buf buf0, buf1, buf2, buf3;
    load(buf0, 0);
    load(buf1, 1);

    int bs = 0;
    const int rcol  = tid & 63;        // reducer's column
    const int rts   = (tid >> 6) & 3;  // reducer's step-in-block
    float* outbase  = out + vhalf * 64 + rcol;

    for (int tb = 0; tb < TT; tb += 4) {
        float4 sa = *reinterpret_cast<const float4*>(alpha + bT + tb);
        float4 sr = *reinterpret_cast<const float4*>(rho   + bT + tb);
        float4 sl = *reinterpret_cast<const float4*>(lam   + bT + tb);

        load(buf2, tb + 2);
        step(buf0, sa.x, sr.x, sl.x, 0, bs);

        int t3 = tb + 3; if (t3 > TT - 1) t3 = TT - 1;
        load(buf3, t3);
        step(buf1, sa.y, sr.y, sl.y, 1, bs);

        int t4 = tb + 4; if (t4 > TT - 1) t4 = TT - 1;
        load(buf0, t4);
        step(buf2, sa.z, sr.z, sl.z, 2, bs);

        int t5 = tb + 5; if (t5 > TT - 1) t5 = TT - 1;
        load(buf1, t5);
        step(buf3, sa.w, sr.w, sl.w, 3, bs);

        __syncthreads();   // block's partials visible; also protects buffer reuse

        if (tid < 256) {
            // 16-way add across warps for (t = tb + rts, col = rcol)
            float s = 0.f;
            #pragma unroll
            for (int w8 = 0; w8 < 16; w8++)
                s += part[bs][rts][w8][rcol];
            outbase[(bT + (size_t)(tb + rts)) * DV] = s;
        }
        bs ^= 1;
    }
}

extern "C" void kernel_launch(void* const* d_in, const int* in_sizes, int n_in,
                              void* d_out, int out_size)
{
    const float* q     = (const float*)d_in[0];
    const float* k     = (const float*)d_in[1];
    const float* v     = (const float*)d_in[2];
    const float* alpha = (const float*)d_in[3];
    const float* rho   = (const float*)d_in[4];
    const float* lam   = (const float*)d_in[5];
    const float* init  = (const float*)d_in[6];
    float* out = (float*)d_out;
    (void)in_sizes; (void)n_in; (void)out_size;

    lmm_scan_kernel<<<BB * 2, 512>>>(q, k, v, alpha, rho, lam, init, out);
}

// round 7
// speedup vs baseline: 1.0116x; 1.0116x over previous
#include <cuda_runtime.h>

#define BB 64
#define TT 2048
#define DK 128
#define DV 128

// ---- packed f32x2 helpers (SASS FFMA2 path — PTX-only) ----
__device__ __forceinline__ unsigned long long pk2(float lo, float hi) {
    unsigned long long r;
    asm("mov.b64 %0, {%1,%2};" : "=l"(r) : "f"(lo), "f"(hi));
    return r;
}
__device__ __forceinline__ unsigned long long fma2(unsigned long long a, unsigned long long b, unsigned long long c) {
    unsigned long long d;
    asm("fma.rn.f32x2 %0, %1, %2, %3;" : "=l"(d) : "l"(a), "l"(b), "l"(c));
    return d;
}
__device__ __forceinline__ unsigned long long mul2_(unsigned long long a, unsigned long long b) {
    unsigned long long d;
    asm("mul.rn.f32x2 %0, %1, %2;" : "=l"(d) : "l"(a), "l"(b));
    return d;
}
__device__ __forceinline__ float2 up2(unsigned long long a) {
    float2 f;
    asm("mov.b64 {%0,%1}, %2;" : "=f"(f.x), "=f"(f.y) : "l"(a));
    return f;
}

struct Buf {
    unsigned long long q2[4];  // this warp's 8 q floats (k rows [8w,8w+8)), packed pairwise
    unsigned long long k2[4];  // this warp's 8 k floats
    float2 v2;                 // lane's 2 v columns
};

__global__ void __launch_bounds__(512, 1)
lmm_scan_kernel(const float* __restrict__ q,
                const float* __restrict__ k,
                const float* __restrict__ v,
                const float* __restrict__ alpha,
                const float* __restrict__ rho,
                const float* __restrict__ lam,
                const float* __restrict__ init,
                float* __restrict__ out)
{
    // CTA = (batch, v-half). 16 warps; warp w owns k rows [8w,8w+8) x 64 v cols.
    // Lane owns 8k x 2v = 8 packed regs. No shuffles, no global atomics:
    // partial sums over each warp's 8 k-rows go to smem; every 4 steps one
    // __syncthreads + 16-way add + coalesced STG (double-buffered smem).
    __shared__ float part[2][4][16][64];   // [buf][step-in-block][warp][vcol] = 32 KB

    const int bid   = blockIdx.x;
    const int b     = bid >> 1;
    const int vhalf = bid & 1;
    const int tid   = threadIdx.x;
    const int warp  = tid >> 5;
    const int lane  = tid & 31;
    const int krow  = warp * 8;                 // warp's 8 k rows
    const int vcol  = vhalf * 64 + lane * 2;    // lane's 2 v columns

    // ---- state M[krow..krow+8) x [vcol..vcol+2), packed pairwise along k ----
    unsigned long long M2[4][2];
    {
        const float* ist = init + (size_t)b * DK * DV;
        #pragma unroll
        for (int kp = 0; kp < 4; kp++) {
            const float* r0 = ist + (size_t)(krow + 2 * kp) * DV + vcol;
            const float* r1 = r0 + DV;
            M2[kp][0] = pk2(r0[0], r1[0]);
            M2[kp][1] = pk2(r0[1], r1[1]);
        }
    }

    const size_t bT = (size_t)b * TT;

    auto load = [&](Buf& bf, int t) {
        size_t roff = (bT + (size_t)t) * DK;
        // warp-uniform 32B loads (all lanes same address -> 1 line each)
        const ulonglong2* qp = reinterpret_cast<const ulonglong2*>(q + roff + krow);
        ulonglong2 x = qp[0], y = qp[1];
        bf.q2[0] = x.x; bf.q2[1] = x.y; bf.q2[2] = y.x; bf.q2[3] = y.y;
        const ulonglong2* kp_ = reinterpret_cast<const ulonglong2*>(k + roff + krow);
        x = kp_[0]; y = kp_[1];
        bf.k2[0] = x.x; bf.k2[1] = x.y; bf.k2[2] = y.x; bf.k2[3] = y.y;
        bf.v2 = *reinterpret_cast<const float2*>(v + roff + vcol);
    };

    auto step = [&](const Buf& bf, float sA, float sR, float sL, int ts, int bs) {
        float w = sA * sR;
        unsigned long long l2  = pk2(sL, sL);
        float w0 = w * bf.v2.x, w1 = w * bf.v2.y;
        unsigned long long wv0 = pk2(w0, w0);
        unsigned long long wv1 = pk2(w1, w1);
        unsigned long long racc0, racc1;
        #pragma unroll
        for (int kp = 0; kp < 4; kp++) {
            unsigned long long t0 = mul2_(bf.k2[kp], wv0);      // (w*v0)*k
            M2[kp][0] = fma2(l2, M2[kp][0], t0);                // M = l*M + wv*k
            racc0 = (kp == 0) ? mul2_(bf.q2[0], M2[0][0])       // r += q*M (post-update)
                              : fma2(bf.q2[kp], M2[kp][0], racc0);
            unsigned long long t1 = mul2_(bf.k2[kp], wv1);
            M2[kp][1] = fma2(l2, M2[kp][1], t1);
            racc1 = (kp == 0) ? mul2_(bf.q2[0], M2[0][1])
                              : fma2(bf.q2[kp], M2[kp][1], racc1);
        }
        float r0, r1;
        { float2 u = up2(racc0); r0 = u.x + u.y; }
        { float2 u = up2(racc1); r1 = u.x + u.y; }
        // partial over this warp's 8 k rows -> smem (conflict-free float2)
        *reinterpret_cast<float2*>(&part[bs][ts][warp][lane * 2]) = make_float2(r0, r1);
    };

    Buf buf0, buf1, buf2, buf3;
    load(buf0, 0);
    load(buf1, 1);

    int bs = 0;
    const int rcol  = tid & 63;        // reducer's column
    const int rts   = (tid >> 6) & 3;  // reducer's step-in-block
    float* outbase  = out + vhalf * 64 + rcol;

    for (int tb = 0; tb < TT; tb += 4) {
        float4 sa = *reinterpret_cast<const float4*>(alpha + bT + tb);
        float4 sr = *reinterpret_cast<const float4*>(rho   + bT + tb);
        float4 sl = *reinterpret_cast<const float4*>(lam   + bT + tb);

        load(buf2, tb + 2);
        step(buf0, sa.x, sr.x, sl.x, 0, bs);

        int t3 = tb + 3; if (t3 > TT - 1) t3 = TT - 1;
        load(buf3, t3);
        step(buf1, sa.y, sr.y, sl.y, 1, bs);

        int t4 = tb + 4; if (t4 > TT - 1) t4 = TT - 1;
        load(buf0, t4);
        step(buf2, sa.z, sr.z, sl.z, 2, bs);

        int t5 = tb + 5; if (t5 > TT - 1) t5 = TT - 1;
        load(buf1, t5);
        step(buf3, sa.w, sr.w, sl.w, 3, bs);

        __syncthreads();   // block's partials visible; also protects buffer reuse

        if (tid < 256) {
            // 16-way add across warps for (t = tb + rts, col = rcol)
            float s = 0.f;
            #pragma unroll
            for (int w8 = 0; w8 < 16; w8++)
                s += part[bs][rts][w8][rcol];
            outbase[(bT + (size_t)(tb + rts)) * DV] = s;
        }
        bs ^= 1;
    }
}

extern "C" void kernel_launch(void* const* d_in, const int* in_sizes, int n_in,
                              void* d_out, int out_size)
{
    const float* q     = (const float*)d_in[0];
    const float* k     = (const float*)d_in[1];
    const float* v     = (const float*)d_in[2];
    const float* alpha = (const float*)d_in[3];
    const float* rho   = (const float*)d_in[4];
    const float* lam   = (const float*)d_in[5];
    const float* init  = (const float*)d_in[6];
    float* out = (float*)d_out;
    (void)in_sizes; (void)n_in; (void)out_size;

    lmm_scan_kernel<<<BB * 2, 512>>>(q, k, v, alpha, rho, lam, init, out);
}

// round 9
// speedup vs baseline: 1.4250x; 1.4086x over previous
#include <cuda_runtime.h>
#include <cuda_bf16.h>
#include <cstdint>

#define TT 2048
#define CC 64
#define NCH 32

// ---- smem byte offsets (strides: 128-col tiles 272B/row, 64-col tiles 144B/row) ----
#define S_QH 0
#define S_QL 17408
#define S_KH 34816
#define S_KL 52224
#define S_MH 69632
#define S_ML 87040
#define S_VH 104448
#define S_VL 113664
#define S_AH 122880
#define S_AL 132096
#define S_TH 141312
#define S_TL 159744
#define S_M0 178176
#define S_G  210944
#define S_WS 211200
#define S_WG 211456
#define S_EG 211712
#define S_SC 211968
#define SMEMB 212224

static __device__ __forceinline__ uint32_t su32(const void* p) {
    uint32_t a;
    asm("{ .reg .u64 t; cvta.to.shared.u64 t, %1; cvt.u32.u64 %0, t; }" : "=r"(a) : "l"(p));
    return a;
}
static __device__ __forceinline__ void ldmA(uint32_t a[4], uint32_t addr) {
    asm volatile("ldmatrix.sync.aligned.m8n8.x4.shared.b16 {%0,%1,%2,%3}, [%4];"
        : "=r"(a[0]), "=r"(a[1]), "=r"(a[2]), "=r"(a[3]) : "r"(addr));
}
static __device__ __forceinline__ void ldmB(uint32_t b[2], uint32_t addr) {
    asm volatile("ldmatrix.sync.aligned.m8n8.x2.shared.b16 {%0,%1}, [%2];"
        : "=r"(b[0]), "=r"(b[1]) : "r"(addr));
}
static __device__ __forceinline__ void mma16(float c[4], const uint32_t a[4], const uint32_t b[2]) {
    asm volatile("mma.sync.aligned.m16n8k16.row.col.f32.bf16.bf16.f32 "
        "{%0,%1,%2,%3}, {%4,%5,%6,%7}, {%8,%9}, {%0,%1,%2,%3};"
        : "+f"(c[0]), "+f"(c[1]), "+f"(c[2]), "+f"(c[3])
        : "r"(a[0]), "r"(a[1]), "r"(a[2]), "r"(a[3]), "r"(b[0]), "r"(b[1]));
}
// split fp32 -> (hi, lo) bf16
static __device__ __forceinline__ void spl(float x, __nv_bfloat16& h, __nv_bfloat16& l) {
    h = __float2bfloat16_rn(x);
    l = __float2bfloat16_rn(x - __bfloat162float(h));
}
static __device__ __forceinline__ void sp2(float x0, float x1, uint32_t& hi, uint32_t& lo) {
    __nv_bfloat16 h0, l0, h1, l1;
    spl(x0, h0, l0); spl(x1, h1, l1);
    hi = (uint32_t)__bfloat16_as_ushort(h0) | ((uint32_t)__bfloat16_as_ushort(h1) << 16);
    lo = (uint32_t)__bfloat16_as_ushort(l0) | ((uint32_t)__bfloat16_as_ushort(l1) << 16);
}
// exp2(x) for x <= 0, FFMA-only (no MUFU): deg-6 Taylor + exponent stuff
static __device__ __forceinline__ float ex2n(float x) {
    float xc = fmaxf(x, -150.f);
    float xf = floorf(xc);
    float f  = xc - xf;
    float p = 1.54035e-4f;
    p = fmaf(p, f, 1.3335581e-3f);
    p = fmaf(p, f, 9.6181291e-3f);
    p = fmaf(p, f, 5.5504109e-2f);
    p = fmaf(p, f, 2.4022651e-1f);
    p = fmaf(p, f, 6.9314718e-1f);
    p = fmaf(p, f, 1.0f);
    float r = __int_as_float(__float_as_int(p) + (((int)xf) << 23));
    return (xc <= -126.f) ? 0.f : r;
}

__global__ void __launch_bounds__(256, 1)
lmm_hmma(const float* __restrict__ q, const float* __restrict__ kk,
         const float* __restrict__ v, const float* __restrict__ alpha,
         const float* __restrict__ rho, const float* __restrict__ lam,
         const float* __restrict__ init, float* __restrict__ out)
{
    extern __shared__ char sm[];
    const uint32_t sb = su32(sm);
    const int tid = threadIdx.x, warp = tid >> 5, lane = tid & 31;
    const int gid = lane >> 2, tig = lane & 3;
    const int b = blockIdx.x >> 1, vh = blockIdx.x & 1;
    const int m0r = (warp >> 1) * 16;      // warp's row tile (S/QM0/AV)
    const int n0s = (warp & 1) * 32;       // warp's col tile
    float* Gs  = (float*)(sm + S_G);
    float* WSs = (float*)(sm + S_WS);
    float* WGs = (float*)(sm + S_WG);
    float* EGs = (float*)(sm + S_EG);
    float* m0f = (float*)(sm + S_M0);

    // ldmatrix lane offsets
    const uint32_t laneA272 = (uint32_t)(lane & 15) * 272u + (uint32_t)((lane >> 4) << 4);
    const uint32_t laneA144 = (uint32_t)(lane & 15) * 144u + (uint32_t)((lane >> 4) << 4);
    const uint32_t laneB272 = (uint32_t)(lane & 7) * 272u + (uint32_t)(((lane >> 3) & 1) << 4);
    const uint32_t laneB144 = (uint32_t)(lane & 7) * 144u + (uint32_t)(((lane >> 3) & 1) << 4);

    // ---- init M0 fp32 in smem ----
    for (int i = tid; i < 2048; i += 256) {
        int m = i >> 4, n4 = (i & 15) << 2;
        *(float4*)(m0f + m * 64 + n4) =
            *(const float4*)(init + (size_t)b * 16384 + (size_t)m * 128 + vh * 64 + n4);
    }
    __syncthreads();

    for (int c = 0; c < NCH; c++) {
        const size_t tb0 = (size_t)b * TT + (size_t)c * CC;

        // ---- scalars (warp 0): inclusive prefix of log2(lam) ----
        if (warp == 0) {
            float x = log2f(fmaxf(lam[tb0 + lane], 1e-37f));
            #pragma unroll
            for (int o = 1; o < 32; o <<= 1) { float y = __shfl_up_sync(~0u, x, o); if (lane >= o) x += y; }
            float tot = __shfl_sync(~0u, x, 31);
            float y2 = log2f(fmaxf(lam[tb0 + 32 + lane], 1e-37f));
            #pragma unroll
            for (int o = 1; o < 32; o <<= 1) { float y = __shfl_up_sync(~0u, y2, o); if (lane >= o) y2 += y; }
            float g2 = tot + y2;
            float g63 = __shfl_sync(~0u, g2, 31);
            float w0 = rho[tb0 + lane] * alpha[tb0 + lane];
            float w1 = rho[tb0 + 32 + lane] * alpha[tb0 + 32 + lane];
            Gs[lane] = x;            Gs[32 + lane] = g2;
            WSs[lane] = w0;          WSs[32 + lane] = w1;
            EGs[lane] = ex2n(x);     EGs[32 + lane] = ex2n(g2);
            WGs[lane] = ex2n(g63 - x) * w0;
            WGs[32 + lane] = ex2n(g63 - g2) * w1;
            if (lane == 31) *(float*)(sm + S_SC) = ex2n(g63);
        }
        // ---- build Q, K split tiles [64t x 128k] ----
        for (int i = tid; i < 2048; i += 256) {
            int t = i >> 5, c4 = (i & 31) << 2;
            uint32_t o = (uint32_t)t * 272u + (uint32_t)(c4 << 1);
            float4 f = *(const float4*)(q + (tb0 + t) * 128 + c4);
            uint32_t h0, l0, h1, l1;
            sp2(f.x, f.y, h0, l0); sp2(f.z, f.w, h1, l1);
            *(uint32_t*)(sm + S_QH + o) = h0; *(uint32_t*)(sm + S_QH + o + 4) = h1;
            *(uint32_t*)(sm + S_QL + o) = l0; *(uint32_t*)(sm + S_QL + o + 4) = l1;
            f = *(const float4*)(kk + (tb0 + t) * 128 + c4);
            sp2(f.x, f.y, h0, l0); sp2(f.z, f.w, h1, l1);
            *(uint32_t*)(sm + S_KH + o) = h0; *(uint32_t*)(sm + S_KH + o + 4) = h1;
            *(uint32_t*)(sm + S_KL + o) = l0; *(uint32_t*)(sm + S_KL + o + 4) = l1;
        }
        // ---- V^T split tiles [64n x 64s] ----
        for (int i = tid; i < 4096; i += 256) {
            int s = i >> 6, n = i & 63;
            __nv_bfloat16 h, l; spl(v[(tb0 + s) * 128 + vh * 64 + n], h, l);
            uint32_t o = (uint32_t)n * 144u + (uint32_t)(s << 1);
            *(__nv_bfloat16*)(sm + S_VH + o) = h;
            *(__nv_bfloat16*)(sm + S_VL + o) = l;
        }
        // ---- M0^T split tiles [64n x 128m] ----
        for (int i = tid; i < 8192; i += 256) {
            int m = i >> 6, n = i & 63;
            __nv_bfloat16 h, l; spl(m0f[m * 64 + n], h, l);
            uint32_t o = (uint32_t)n * 272u + (uint32_t)(m << 1);
            *(__nv_bfloat16*)(sm + S_MH + o) = h;
            *(__nv_bfloat16*)(sm + S_ML + o) = l;
        }
        __syncthreads();

        // ---- GEMM1: S = Q K^T  and  QM0 = Q M0   (K=128) ----
        float sS[4][4], sQ[4][4];
        #pragma unroll
        for (int j = 0; j < 4; j++)
            #pragma unroll
            for (int e = 0; e < 4; e++) { sS[j][e] = 0.f; sQ[j][e] = 0.f; }
        {
            const uint32_t qhB = sb + S_QH + (uint32_t)m0r * 272u + laneA272;
            const uint32_t qlB = qhB + (S_QL - S_QH);
            #pragma unroll
            for (int ks = 0; ks < 8; ks++) {
                uint32_t qa[4], ql[4];
                ldmA(qa, qhB + ks * 32); ldmA(ql, qlB + ks * 32);
                #pragma unroll
                for (int j = 0; j < 4; j++) {
                    uint32_t bh[2], bl[2];
                    uint32_t kB = sb + S_KH + (uint32_t)(n0s + 8 * j) * 272u + ks * 32 + laneB272;
                    ldmB(bh, kB); ldmB(bl, kB + (S_KL - S_KH));
                    mma16(sS[j], qa, bh); mma16(sS[j], qa, bl); mma16(sS[j], ql, bh);
                    uint32_t mB = sb + S_MH + (uint32_t)(n0s + 8 * j) * 272u + ks * 32 + laneB272;
                    ldmB(bh, mB); ldmB(bl, mB + (S_ML - S_MH));
                    mma16(sQ[j], qa, bh); mma16(sQ[j], qa, bl); mma16(sQ[j], ql, bh);
                }
            }
        }
        // ---- A build: A[t,s] = exp2(G_t - G_s) * w_s * S[t,s]  (t>=s) ----
        {
            int t0 = m0r + gid, t1 = t0 + 8;
            float g0 = Gs[t0], g1 = Gs[t1];
            #pragma unroll
            for (int j = 0; j < 4; j++) {
                int s0 = n0s + 8 * j + 2 * tig, s1 = s0 + 1;
                float gs0 = Gs[s0], gs1 = Gs[s1], w0 = WSs[s0], w1 = WSs[s1];
                float a00 = (t0 >= s0) ? ex2n(g0 - gs0) * w0 * sS[j][0] : 0.f;
                float a01 = (t0 >= s1) ? ex2n(g0 - gs1) * w1 * sS[j][1] : 0.f;
                float a10 = (t1 >= s0) ? ex2n(g1 - gs0) * w0 * sS[j][2] : 0.f;
                float a11 = (t1 >= s1) ? ex2n(g1 - gs1) * w1 * sS[j][3] : 0.f;
                uint32_t hi, lo;
                sp2(a00, a01, hi, lo);
                uint32_t o = (uint32_t)t0 * 144u + (uint32_t)(s0 << 1);
                *(uint32_t*)(sm + S_AH + o) = hi; *(uint32_t*)(sm + S_AL + o) = lo;
                sp2(a10, a11, hi, lo);
                o = (uint32_t)t1 * 144u + (uint32_t)(s0 << 1);
                *(uint32_t*)(sm + S_AH + o) = hi; *(uint32_t*)(sm + S_AL + o) = lo;
            }
        }
        // ---- KT build: KT[m][s] = WG_s * k_s[m]  (split) ----
        for (int i = tid; i < 8192; i += 256) {
            int m = i >> 6, s = i & 63;
            uint32_t ko = (uint32_t)s * 272u + (uint32_t)(m << 1);
            float hv = __bfloat162float(*(__nv_bfloat16*)(sm + S_KH + ko));
            float lv = __bfloat162float(*(__nv_bfloat16*)(sm + S_KL + ko));
            __nv_bfloat16 h, l; spl((hv + lv) * WGs[s], h, l);
            uint32_t o = (uint32_t)m * 144u + (uint32_t)(s << 1);
            *(__nv_bfloat16*)(sm + S_TH + o) = h;
            *(__nv_bfloat16*)(sm + S_TL + o) = l;
        }
        __syncthreads();

        // ---- GEMM2: AV = A V  (K=64)  and  dM = KT V  (K=64) ----
        float sA[4][4], sD[8][4];
        #pragma unroll
        for (int j = 0; j < 4; j++)
            #pragma unroll
            for (int e = 0; e < 4; e++) sA[j][e] = 0.f;
        #pragma unroll
        for (int j = 0; j < 8; j++)
            #pragma unroll
            for (int e = 0; e < 4; e++) sD[j][e] = 0.f;
        {
            const uint32_t ahB = sb + S_AH + (uint32_t)m0r * 144u + laneA144;
            #pragma unroll
            for (int ks = 0; ks < 4; ks++) {
                uint32_t aa[4], al[4];
                ldmA(aa, ahB + ks * 32); ldmA(al, ahB + (S_AL - S_AH) + ks * 32);
                #pragma unroll
                for (int j = 0; j < 4; j++) {
                    uint32_t bh[2], bl[2];
                    uint32_t vB = sb + S_VH + (uint32_t)(n0s + 8 * j) * 144u + ks * 32 + laneB144;
                    ldmB(bh, vB); ldmB(bl, vB + (S_VL - S_VH));
                    mma16(sA[j], aa, bh); mma16(sA[j], aa, bl); mma16(sA[j], al, bh);
                }
            }
            const uint32_t ktB = sb + S_TH + (uint32_t)(warp * 16) * 144u + laneA144;
            #pragma unroll
            for (int ks = 0; ks < 4; ks++) {
                uint32_t ka[4], kl2[4];
                ldmA(ka, ktB + ks * 32); ldmA(kl2, ktB + (S_TL - S_TH) + ks * 32);
                #pragma unroll
                for (int j = 0; j < 8; j++) {
                    uint32_t bh[2], bl[2];
                    uint32_t vB = sb + S_VH + (uint32_t)(8 * j) * 144u + ks * 32 + laneB144;
                    ldmB(bh, vB); ldmB(bl, vB + (S_VL - S_VH));
                    mma16(sD[j], ka, bh); mma16(sD[j], ka, bl); mma16(sD[j], kl2, bh);
                }
            }
        }
        // ---- epilogue: readout r = EG_t * QM0 + AV ----
        {
            int t0 = m0r + gid, t1 = t0 + 8;
            float e0 = EGs[t0], e1 = EGs[t1];
            #pragma unroll
            for (int j = 0; j < 4; j++) {
                int n = n0s + 8 * j + 2 * tig;
                float2 o0 = make_float2(fmaf(e0, sQ[j][0], sA[j][0]), fmaf(e0, sQ[j][1], sA[j][1]));
                float2 o1 = make_float2(fmaf(e1, sQ[j][2], sA[j][2]), fmaf(e1, sQ[j][3], sA[j][3]));
                *(float2*)(out + (tb0 + t0) * 128 + vh * 64 + n) = o0;
                *(float2*)(out + (tb0 + t1) * 128 + vh * 64 + n) = o1;
            }
        }
        // ---- epilogue: M0 = s63 * M0 + dM ----
        {
            float s63 = *(float*)(sm + S_SC);
            int mr0 = warp * 16 + gid, mr1 = mr0 + 8;
            #pragma unroll
            for (int j = 0; j < 8; j++) {
                int n = 8 * j + 2 * tig;
                float2* p0 = (float2*)(m0f + mr0 * 64 + n);
                float2* p1 = (float2*)(m0f + mr1 * 64 + n);
                float2 u0 = *p0, u1 = *p1;
                u0.x = fmaf(s63, u0.x, sD[j][0]); u0.y = fmaf(s63, u0.y, sD[j][1]);
                u1.x = fmaf(s63, u1.x, sD[j][2]); u1.y = fmaf(s63, u1.y, sD[j][3]);
                *p0 = u0; *p1 = u1;
            }
        }
        __syncthreads();
    }
}

extern "C" void kernel_launch(void* const* d_in, const int* in_sizes, int n_in,
                              void* d_out, int out_size)
{
    (void)in_sizes; (void)n_in; (void)out_size;
    cudaFuncSetAttribute(lmm_hmma, cudaFuncAttributeMaxDynamicSharedMemorySize, SMEMB);
    lmm_hmma<<<128, 256, SMEMB>>>((const float*)d_in[0], (const float*)d_in[1],
                                  (const float*)d_in[2], (const float*)d_in[3],
                                  (const float*)d_in[4], (const float*)d_in[5],
                                  (const float*)d_in[6], (float*)d_out);
}

// round 10
// speedup vs baseline: 1.7929x; 1.2582x over previous
#include <cuda_runtime.h>
#include <cuda_bf16.h>
#include <cstdint>

#define TT 2048
#define CC 64
#define NCH 32
#define NT 512

// ---- smem byte offsets (strides: 128-col tiles 272B/row, 64-col tiles 144B/row) ----
#define S_QH 0
#define S_QL 17408
#define S_KH 34816
#define S_KL 52224
#define S_MH 69632
#define S_ML 87040
#define S_VH 104448
#define S_VL 113664
#define S_AH 122880
#define S_AL 132096
#define S_TH 141312
#define S_TL 159744
#define S_M0 178176
#define S_G  210944
#define S_WS 211200
#define S_WG 211456
#define S_EG 211712
#define S_SC 211968
#define SMEMB 212224

static __device__ __forceinline__ uint32_t su32(const void* p) {
    uint32_t a;
    asm("{ .reg .u64 t; cvta.to.shared.u64 t, %1; cvt.u32.u64 %0, t; }" : "=r"(a) : "l"(p));
    return a;
}
static __device__ __forceinline__ void ldmA(uint32_t a[4], uint32_t addr) {
    asm volatile("ldmatrix.sync.aligned.m8n8.x4.shared.b16 {%0,%1,%2,%3}, [%4];"
        : "=r"(a[0]), "=r"(a[1]), "=r"(a[2]), "=r"(a[3]) : "r"(addr));
}
static __device__ __forceinline__ void ldmB(uint32_t b[2], uint32_t addr) {
    asm volatile("ldmatrix.sync.aligned.m8n8.x2.shared.b16 {%0,%1}, [%2];"
        : "=r"(b[0]), "=r"(b[1]) : "r"(addr));
}
static __device__ __forceinline__ void mma16(float c[4], const uint32_t a[4], const uint32_t b[2]) {
    asm volatile("mma.sync.aligned.m16n8k16.row.col.f32.bf16.bf16.f32 "
        "{%0,%1,%2,%3}, {%4,%5,%6,%7}, {%8,%9}, {%0,%1,%2,%3};"
        : "+f"(c[0]), "+f"(c[1]), "+f"(c[2]), "+f"(c[3])
        : "r"(a[0]), "r"(a[1]), "r"(a[2]), "r"(a[3]), "r"(b[0]), "r"(b[1]));
}
static __device__ __forceinline__ void spl(float x, __nv_bfloat16& h, __nv_bfloat16& l) {
    h = __float2bfloat16_rn(x);
    l = __float2bfloat16_rn(x - __bfloat162float(h));
}
static __device__ __forceinline__ void sp2(float x0, float x1, uint32_t& hi, uint32_t& lo) {
    __nv_bfloat16 h0, l0, h1, l1;
    spl(x0, h0, l0); spl(x1, h1, l1);
    hi = (uint32_t)__bfloat16_as_ushort(h0) | ((uint32_t)__bfloat16_as_ushort(h1) << 16);
    lo = (uint32_t)__bfloat16_as_ushort(l0) | ((uint32_t)__bfloat16_as_ushort(l1) << 16);
}
// exp2(x) for x <= 0, FFMA-only: floor + deg-6 poly + exponent stuffing
static __device__ __forceinline__ float ex2n(float x) {
    float xc = fmaxf(x, -150.f);
    float xf = floorf(xc);
    float f  = xc - xf;
    float p = 1.54035e-4f;
    p = fmaf(p, f, 1.3335581e-3f);
    p = fmaf(p, f, 9.6181291e-3f);
    p = fmaf(p, f, 5.5504109e-2f);
    p = fmaf(p, f, 2.4022651e-1f);
    p = fmaf(p, f, 6.9314718e-1f);
    p = fmaf(p, f, 1.0f);
    float r = __int_as_float(__float_as_int(p) + (((int)xf) << 23));
    return (xc <= -126.f) ? 0.f : r;
}

__global__ void __launch_bounds__(NT, 1)
lmm_hmma(const float* __restrict__ q, const float* __restrict__ kk,
         const float* __restrict__ v, const float* __restrict__ alpha,
         const float* __restrict__ rho, const float* __restrict__ lam,
         const float* __restrict__ init, float* __restrict__ out)
{
    extern __shared__ char sm[];
    const uint32_t sb = su32(sm);
    const int tid = threadIdx.x, warp = tid >> 5, lane = tid & 31;
    const int gid = lane >> 2, tig = lane & 3;
    const int b = blockIdx.x >> 1, vh = blockIdx.x & 1;
    const int rt = warp >> 2, ct = warp & 3;   // 16x16 tile for S/QM0/AV
    const int wr = warp >> 1, wc = warp & 1;   // 16x32 tile for dM/M0
    float* Gs  = (float*)(sm + S_G);
    float* WSs = (float*)(sm + S_WS);
    float* WGs = (float*)(sm + S_WG);
    float* EGs = (float*)(sm + S_EG);
    float* m0f = (float*)(sm + S_M0);

    const uint32_t laneA272 = (uint32_t)(lane & 15) * 272u + (uint32_t)((lane >> 4) << 4);
    const uint32_t laneA144 = (uint32_t)(lane & 15) * 144u + (uint32_t)((lane >> 4) << 4);
    const uint32_t laneB272 = (uint32_t)(lane & 7) * 272u + (uint32_t)(((lane >> 3) & 1) << 4);
    const uint32_t laneB144 = (uint32_t)(lane & 7) * 144u + (uint32_t)(((lane >> 3) & 1) << 4);

    // ---- init M0 fp32 in smem ----
    for (int i = tid; i < 2048; i += NT) {
        int m = i >> 4, n4 = (i & 15) << 2;
        *(float4*)(m0f + m * 64 + n4) =
            *(const float4*)(init + (size_t)b * 16384 + (size_t)m * 128 + vh * 64 + n4);
    }
    __syncthreads();

    for (int c = 0; c < NCH; c++) {
        const size_t tb0 = (size_t)b * TT + (size_t)c * CC;

        // ---- scalars (warp 0) ----
        if (warp == 0) {
            float x = log2f(fmaxf(lam[tb0 + lane], 1e-37f));
            #pragma unroll
            for (int o = 1; o < 32; o <<= 1) { float y = __shfl_up_sync(~0u, x, o); if (lane >= o) x += y; }
            float tot = __shfl_sync(~0u, x, 31);
            float y2 = log2f(fmaxf(lam[tb0 + 32 + lane], 1e-37f));
            #pragma unroll
            for (int o = 1; o < 32; o <<= 1) { float y = __shfl_up_sync(~0u, y2, o); if (lane >= o) y2 += y; }
            float g2 = tot + y2;
            float g63 = __shfl_sync(~0u, g2, 31);
            float w0 = rho[tb0 + lane] * alpha[tb0 + lane];
            float w1 = rho[tb0 + 32 + lane] * alpha[tb0 + 32 + lane];
            Gs[lane] = x;            Gs[32 + lane] = g2;
            WSs[lane] = w0;          WSs[32 + lane] = w1;
            EGs[lane] = ex2n(x);     EGs[32 + lane] = ex2n(g2);
            WGs[lane] = ex2n(g63 - x) * w0;
            WGs[32 + lane] = ex2n(g63 - g2) * w1;
            if (lane == 31) *(float*)(sm + S_SC) = ex2n(g63);
        }
        // ---- Q, K split tiles [64t x 128k] ----
        for (int i = tid; i < 2048; i += NT) {
            int t = i >> 5, c4 = (i & 31) << 2;
            uint32_t o = (uint32_t)t * 272u + (uint32_t)(c4 << 1);
            float4 f = *(const float4*)(q + (tb0 + t) * 128 + c4);
            uint32_t h0, l0, h1, l1;
            sp2(f.x, f.y, h0, l0); sp2(f.z, f.w, h1, l1);
            *(uint32_t*)(sm + S_QH + o) = h0; *(uint32_t*)(sm + S_QH + o + 4) = h1;
            *(uint32_t*)(sm + S_QL + o) = l0; *(uint32_t*)(sm + S_QL + o + 4) = l1;
            f = *(const float4*)(kk + (tb0 + t) * 128 + c4);
            sp2(f.x, f.y, h0, l0); sp2(f.z, f.w, h1, l1);
            *(uint32_t*)(sm + S_KH + o) = h0; *(uint32_t*)(sm + S_KH + o + 4) = h1;
            *(uint32_t*)(sm + S_KL + o) = l0; *(uint32_t*)(sm + S_KL + o + 4) = l1;
        }
        // ---- V^T split tiles [64n x 64s] ----
        for (int i = tid; i < 4096; i += NT) {
            int s = i >> 6, n = i & 63;
            __nv_bfloat16 h, l; spl(v[(tb0 + s) * 128 + vh * 64 + n], h, l);
            uint32_t o = (uint32_t)n * 144u + (uint32_t)(s << 1);
            *(__nv_bfloat16*)(sm + S_VH + o) = h;
            *(__nv_bfloat16*)(sm + S_VL + o) = l;
        }
        // ---- M0^T split tiles [64n x 128m] ----
        for (int i = tid; i < 8192; i += NT) {
            int m = i >> 6, n = i & 63;
            __nv_bfloat16 h, l; spl(m0f[m * 64 + n], h, l);
            uint32_t o = (uint32_t)n * 272u + (uint32_t)(m << 1);
            *(__nv_bfloat16*)(sm + S_MH + o) = h;
            *(__nv_bfloat16*)(sm + S_ML + o) = l;
        }
        __syncthreads();

        // ---- GEMM1: S = Q K^T (only ct<=rt) and QM0 = Q M0 (K=128) ----
        float sS[2][4], sQ[2][4];
        #pragma unroll
        for (int j = 0; j < 2; j++)
            #pragma unroll
            for (int e = 0; e < 4; e++) { sS[j][e] = 0.f; sQ[j][e] = 0.f; }
        {
            const uint32_t qhB = sb + S_QH + (uint32_t)(rt * 16) * 272u + laneA272;
            #pragma unroll
            for (int ks = 0; ks < 8; ks++) {
                uint32_t qa[4], ql[4];
                ldmA(qa, qhB + ks * 32); ldmA(ql, qhB + (S_QL - S_QH) + ks * 32);
                #pragma unroll
                for (int j = 0; j < 2; j++) {
                    uint32_t col = (uint32_t)(ct * 16 + 8 * j);
                    uint32_t bh[2], bl[2];
                    if (ct <= rt) {
                        uint32_t kB = sb + S_KH + col * 272u + ks * 32 + laneB272;
                        ldmB(bh, kB); ldmB(bl, kB + (S_KL - S_KH));
                        mma16(sS[j], qa, bh); mma16(sS[j], qa, bl); mma16(sS[j], ql, bh);
                    }
                    uint32_t mB = sb + S_MH + col * 272u + ks * 32 + laneB272;
                    ldmB(bh, mB); ldmB(bl, mB + (S_ML - S_MH));
                    mma16(sQ[j], qa, bh); mma16(sQ[j], qa, bl); mma16(sQ[j], ql, bh);
                }
            }
        }
        // ---- A build (tiles with ct<=rt only; others never read) ----
        if (ct <= rt) {
            int t0 = rt * 16 + gid, t1 = t0 + 8;
            float g0 = Gs[t0], g1 = Gs[t1];
            #pragma unroll
            for (int j = 0; j < 2; j++) {
                int s0 = ct * 16 + 8 * j + 2 * tig, s1 = s0 + 1;
                float gs0 = Gs[s0], gs1 = Gs[s1], w0 = WSs[s0], w1 = WSs[s1];
                float a00 = (t0 >= s0) ? ex2n(g0 - gs0) * w0 * sS[j][0] : 0.f;
                float a01 = (t0 >= s1) ? ex2n(g0 - gs1) * w1 * sS[j][1] : 0.f;
                float a10 = (t1 >= s0) ? ex2n(g1 - gs0) * w0 * sS[j][2] : 0.f;
                float a11 = (t1 >= s1) ? ex2n(g1 - gs1) * w1 * sS[j][3] : 0.f;
                uint32_t hi, lo;
                sp2(a00, a01, hi, lo);
                uint32_t o = (uint32_t)t0 * 144u + (uint32_t)(s0 << 1);
                *(uint32_t*)(sm + S_AH + o) = hi; *(uint32_t*)(sm + S_AL + o) = lo;
                sp2(a10, a11, hi, lo);
                o = (uint32_t)t1 * 144u + (uint32_t)(s0 << 1);
                *(uint32_t*)(sm + S_AH + o) = hi; *(uint32_t*)(sm + S_AL + o) = lo;
            }
        }
        // ---- KT build: KT[m][s] = WG_s * k_s[m] ----
        for (int i = tid; i < 8192; i += NT) {
            int m = i >> 6, s = i & 63;
            uint32_t ko = (uint32_t)s * 272u + (uint32_t)(m << 1);
            float hv = __bfloat162float(*(__nv_bfloat16*)(sm + S_KH + ko));
            float lv = __bfloat162float(*(__nv_bfloat16*)(sm + S_KL + ko));
            __nv_bfloat16 h, l; spl((hv + lv) * WGs[s], h, l);
            uint32_t o = (uint32_t)m * 144u + (uint32_t)(s << 1);
            *(__nv_bfloat16*)(sm + S_TH + o) = h;
            *(__nv_bfloat16*)(sm + S_TL + o) = l;
        }
        __syncthreads();

        // ---- GEMM2: AV (ks<=rt) and dM = KT V ----
        float sA[2][4], sD[4][4];
        #pragma unroll
        for (int j = 0; j < 2; j++)
            #pragma unroll
            for (int e = 0; e < 4; e++) sA[j][e] = 0.f;
        #pragma unroll
        for (int j = 0; j < 4; j++)
            #pragma unroll
            for (int e = 0; e < 4; e++) sD[j][e] = 0.f;
        {
            const uint32_t ahB = sb + S_AH + (uint32_t)(rt * 16) * 144u + laneA144;
            #pragma unroll
            for (int ks = 0; ks < 4; ks++) {
                if (ks <= rt) {
                    uint32_t aa[4], al[4];
                    ldmA(aa, ahB + ks * 32); ldmA(al, ahB + (S_AL - S_AH) + ks * 32);
                    #pragma unroll
                    for (int j = 0; j < 2; j++) {
                        uint32_t bh[2], bl[2];
                        uint32_t vB = sb + S_VH + (uint32_t)(ct * 16 + 8 * j) * 144u + ks * 32 + laneB144;
                        ldmB(bh, vB); ldmB(bl, vB + (S_VL - S_VH));
                        mma16(sA[j], aa, bh); mma16(sA[j], aa, bl); mma16(sA[j], al, bh);
                    }
                }
            }
            const uint32_t ktB = sb + S_TH + (uint32_t)(wr * 16) * 144u + laneA144;
            #pragma unroll
            for (int ks = 0; ks < 4; ks++) {
                uint32_t ka[4], kl2[4];
                ldmA(ka, ktB + ks * 32); ldmA(kl2, ktB + (S_TL - S_TH) + ks * 32);
                #pragma unroll
                for (int j = 0; j < 4; j++) {
                    uint32_t bh[2], bl[2];
                    uint32_t vB = sb + S_VH + (uint32_t)(wc * 32 + 8 * j) * 144u + ks * 32 + laneB144;
                    ldmB(bh, vB); ldmB(bl, vB + (S_VL - S_VH));
                    mma16(sD[j], ka, bh); mma16(sD[j], ka, bl); mma16(sD[j], kl2, bh);
                }
            }
        }
        // ---- readout r = EG_t * QM0 + AV ----
        {
            int t0 = rt * 16 + gid, t1 = t0 + 8;
            float e0 = EGs[t0], e1 = EGs[t1];
            #pragma unroll
            for (int j = 0; j < 2; j++) {
                int n = ct * 16 + 8 * j + 2 * tig;
                float2 o0 = make_float2(fmaf(e0, sQ[j][0], sA[j][0]), fmaf(e0, sQ[j][1], sA[j][1]));
                float2 o1 = make_float2(fmaf(e1, sQ[j][2], sA[j][2]), fmaf(e1, sQ[j][3], sA[j][3]));
                *(float2*)(out + (tb0 + t0) * 128 + vh * 64 + n) = o0;
                *(float2*)(out + (tb0 + t1) * 128 + vh * 64 + n) = o1;
            }
        }
        // ---- M0 = s63 * M0 + dM ----
        {
            float s63 = *(float*)(sm + S_SC);
            int mr0 = wr * 16 + gid, mr1 = mr0 + 8;
            #pragma unroll
            for (int j = 0; j < 4; j++) {
                int n = wc * 32 + 8 * j + 2 * tig;
                float2* p0 = (float2*)(m0f + mr0 * 64 + n);
                float2* p1 = (float2*)(m0f + mr1 * 64 + n);
                float2 u0 = *p0, u1 = *p1;
                u0.x = fmaf(s63, u0.x, sD[j][0]); u0.y = fmaf(s63, u0.y, sD[j][1]);
                u1.x = fmaf(s63, u1.x, sD[j][2]); u1.y = fmaf(s63, u1.y, sD[j][3]);
                *p0 = u0; *p1 = u1;
            }
        }
        __syncthreads();
    }
}

extern "C" void kernel_launch(void* const* d_in, const int* in_sizes, int n_in,
                              void* d_out, int out_size)
{
    (void)in_sizes; (void)n_in; (void)out_size;
    cudaFuncSetAttribute(lmm_hmma, cudaFuncAttributeMaxDynamicSharedMemorySize, SMEMB);
    lmm_hmma<<<128, NT, SMEMB>>>((const float*)d_in[0], (const float*)d_in[1],
                                 (const float*)d_in[2], (const float*)d_in[3],
                                 (const float*)d_in[4], (const float*)d_in[5],
                                 (const float*)d_in[6], (float*)d_out);
}

// round 11
// speedup vs baseline: 1.9073x; 1.0638x over previous
#include <cuda_runtime.h>
#include <cuda_bf16.h>
#include <cstdint>

#define TT 2048
#define CC 64
#define NCH 32
#define NT 512

// ---- smem byte offsets (strides: 128-col tiles 272B/row, 64-col tiles 144B/row) ----
#define S_QH 0
#define S_QL 17408
#define S_KH 34816
#define S_KL 52224
#define S_MH 69632
#define S_ML 87040
#define S_VH 104448
#define S_VL 113664
#define S_AH 122880
#define S_AL 132096
#define S_TH 141312
#define S_TL 159744
#define S_M0 178176
#define S_G  210944
#define S_WS 211200
#define S_WG 211456
#define S_EG 211712
#define S_SC 211968
#define SMEMB 212224

static __device__ __forceinline__ uint32_t su32(const void* p) {
    uint32_t a;
    asm("{ .reg .u64 t; cvta.to.shared.u64 t, %1; cvt.u32.u64 %0, t; }" : "=r"(a) : "l"(p));
    return a;
}
static __device__ __forceinline__ void ldmA(uint32_t a[4], uint32_t addr) {
    asm volatile("ldmatrix.sync.aligned.m8n8.x4.shared.b16 {%0,%1,%2,%3}, [%4];"
        : "=r"(a[0]), "=r"(a[1]), "=r"(a[2]), "=r"(a[3]) : "r"(addr));
}
// x4 B-load: covers TWO adjacent n8 tiles (j and j+1): {b0,b1} first, {b2,b3} second
static __device__ __forceinline__ void ldmB4(uint32_t b[4], uint32_t addr) {
    asm volatile("ldmatrix.sync.aligned.m8n8.x4.shared.b16 {%0,%1,%2,%3}, [%4];"
        : "=r"(b[0]), "=r"(b[1]), "=r"(b[2]), "=r"(b[3]) : "r"(addr));
}
static __device__ __forceinline__ void mma16(float c[4], const uint32_t a[4], const uint32_t b0, const uint32_t b1) {
    asm volatile("mma.sync.aligned.m16n8k16.row.col.f32.bf16.bf16.f32 "
        "{%0,%1,%2,%3}, {%4,%5,%6,%7}, {%8,%9}, {%0,%1,%2,%3};"
        : "+f"(c[0]), "+f"(c[1]), "+f"(c[2]), "+f"(c[3])
        : "r"(a[0]), "r"(a[1]), "r"(a[2]), "r"(a[3]), "r"(b0), "r"(b1));
}
static __device__ __forceinline__ void spl(float x, __nv_bfloat16& h, __nv_bfloat16& l) {
    h = __float2bfloat16_rn(x);
    l = __float2bfloat16_rn(x - __bfloat162float(h));
}
static __device__ __forceinline__ void sp2(float x0, float x1, uint32_t& hi, uint32_t& lo) {
    __nv_bfloat16 h0, l0, h1, l1;
    spl(x0, h0, l0); spl(x1, h1, l1);
    hi = (uint32_t)__bfloat16_as_ushort(h0) | ((uint32_t)__bfloat16_as_ushort(h1) << 16);
    lo = (uint32_t)__bfloat16_as_ushort(l0) | ((uint32_t)__bfloat16_as_ushort(l1) << 16);
}
// exp2(x) for x <= 0, FFMA-only
static __device__ __forceinline__ float ex2n(float x) {
    float xc = fmaxf(x, -150.f);
    float xf = floorf(xc);
    float f  = xc - xf;
    float p = 1.54035e-4f;
    p = fmaf(p, f, 1.3335581e-3f);
    p = fmaf(p, f, 9.6181291e-3f);
    p = fmaf(p, f, 5.5504109e-2f);
    p = fmaf(p, f, 2.4022651e-1f);
    p = fmaf(p, f, 6.9314718e-1f);
    p = fmaf(p, f, 1.0f);
    float r = __int_as_float(__float_as_int(p) + (((int)xf) << 23));
    return (xc <= -126.f) ? 0.f : r;
}

__global__ void __launch_bounds__(NT, 1)
lmm_hmma(const float* __restrict__ q, const float* __restrict__ kk,
         const float* __restrict__ v, const float* __restrict__ alpha,
         const float* __restrict__ rho, const float* __restrict__ lam,
         const float* __restrict__ init, float* __restrict__ out)
{
    extern __shared__ char sm[];
    const uint32_t sb = su32(sm);
    const int tid = threadIdx.x, warp = tid >> 5, lane = tid & 31;
    const int gid = lane >> 2, tig = lane & 3;
    const int b = blockIdx.x >> 1, vh = blockIdx.x & 1;
    const int rt = warp >> 2, ct = warp & 3;   // 16x16 tile for S/QM0/AV
    const int wr = warp >> 1, wc = warp & 1;   // 16x32 tile for dM/M0
    float* Gs  = (float*)(sm + S_G);
    float* WSs = (float*)(sm + S_WS);
    float* WGs = (float*)(sm + S_WG);
    float* EGs = (float*)(sm + S_EG);
    float* m0f = (float*)(sm + S_M0);

    const uint32_t laneA272 = (uint32_t)(lane & 15) * 272u + (uint32_t)((lane >> 4) << 4);
    const uint32_t laneA144 = (uint32_t)(lane & 15) * 144u + (uint32_t)((lane >> 4) << 4);
    const uint32_t laneB272x4 = (uint32_t)(lane & 7) * 272u + (uint32_t)(((lane >> 3) & 1) << 4)
                              + (uint32_t)(lane >> 4) * (8u * 272u);
    const uint32_t laneB144x4 = (uint32_t)(lane & 7) * 144u + (uint32_t)(((lane >> 3) & 1) << 4)
                              + (uint32_t)(lane >> 4) * (8u * 144u);

    // ---- init M0 fp32 in smem ----
    for (int i = tid; i < 2048; i += NT) {
        int m = i >> 4, n4 = (i & 15) << 2;
        *(float4*)(m0f + m * 64 + n4) =
            *(const float4*)(init + (size_t)b * 16384 + (size_t)m * 128 + vh * 64 + n4);
    }
    __syncthreads();

    for (int c = 0; c < NCH; c++) {
        const size_t tb0 = (size_t)b * TT + (size_t)c * CC;

        // ---- V prefetch (LDGs fly under the whole build + GEMM1 phase) ----
        float vreg[8];
        #pragma unroll
        for (int ii = 0; ii < 8; ii++) {
            int i = tid + ii * NT;
            vreg[ii] = v[(tb0 + (size_t)(i >> 6)) * 128 + vh * 64 + (i & 63)];
        }
        // ---- scalars (warp 0) ----
        if (warp == 0) {
            float x = log2f(fmaxf(lam[tb0 + lane], 1e-37f));
            #pragma unroll
            for (int o = 1; o < 32; o <<= 1) { float y = __shfl_up_sync(~0u, x, o); if (lane >= o) x += y; }
            float tot = __shfl_sync(~0u, x, 31);
            float y2 = log2f(fmaxf(lam[tb0 + 32 + lane], 1e-37f));
            #pragma unroll
            for (int o = 1; o < 32; o <<= 1) { float y = __shfl_up_sync(~0u, y2, o); if (lane >= o) y2 += y; }
            float g2 = tot + y2;
            float g63 = __shfl_sync(~0u, g2, 31);
            float w0 = rho[tb0 + lane] * alpha[tb0 + lane];
            float w1 = rho[tb0 + 32 + lane] * alpha[tb0 + 32 + lane];
            Gs[lane] = x;            Gs[32 + lane] = g2;
            WSs[lane] = w0;          WSs[32 + lane] = w1;
            EGs[lane] = ex2n(x);     EGs[32 + lane] = ex2n(g2);
            WGs[lane] = ex2n(g63 - x) * w0;
            WGs[32 + lane] = ex2n(g63 - g2) * w1;
            if (lane == 31) *(float*)(sm + S_SC) = ex2n(g63);
        }
        // ---- Q, K split tiles [64t x 128k] ----
        for (int i = tid; i < 2048; i += NT) {
            int t = i >> 5, c4 = (i & 31) << 2;
            uint32_t o = (uint32_t)t * 272u + (uint32_t)(c4 << 1);
            float4 f = *(const float4*)(q + (tb0 + t) * 128 + c4);
            uint32_t h0, l0, h1, l1;
            sp2(f.x, f.y, h0, l0); sp2(f.z, f.w, h1, l1);
            *(uint32_t*)(sm + S_QH + o) = h0; *(uint32_t*)(sm + S_QH + o + 4) = h1;
            *(uint32_t*)(sm + S_QL + o) = l0; *(uint32_t*)(sm + S_QL + o + 4) = l1;
            f = *(const float4*)(kk + (tb0 + t) * 128 + c4);
            sp2(f.x, f.y, h0, l0); sp2(f.z, f.w, h1, l1);
            *(uint32_t*)(sm + S_KH + o) = h0; *(uint32_t*)(sm + S_KH + o + 4) = h1;
            *(uint32_t*)(sm + S_KL + o) = l0; *(uint32_t*)(sm + S_KL + o + 4) = l1;
        }
        // ---- M0^T split tiles [64n x 128m] ----
        for (int i = tid; i < 8192; i += NT) {
            int m = i >> 6, n = i & 63;
            __nv_bfloat16 h, l; spl(m0f[m * 64 + n], h, l);
            uint32_t o = (uint32_t)n * 272u + (uint32_t)(m << 1);
            *(__nv_bfloat16*)(sm + S_MH + o) = h;
            *(__nv_bfloat16*)(sm + S_ML + o) = l;
        }
        __syncthreads();

        // ---- GEMM1: S = Q K^T (only ct<=rt) and QM0 = Q M0 (K=128) ----
        float sS[2][4], sQ[2][4];
        #pragma unroll
        for (int j = 0; j < 2; j++)
            #pragma unroll
            for (int e = 0; e < 4; e++) { sS[j][e] = 0.f; sQ[j][e] = 0.f; }
        {
            const uint32_t qhB = sb + S_QH + (uint32_t)(rt * 16) * 272u + laneA272;
            const uint32_t col = (uint32_t)(ct * 16);
            #pragma unroll
            for (int ks = 0; ks < 8; ks++) {
                uint32_t qa[4], ql[4];
                ldmA(qa, qhB + ks * 32); ldmA(ql, qhB + (S_QL - S_QH) + ks * 32);
                if (ct <= rt) {
                    uint32_t bh[4], bl[4];
                    uint32_t kB = sb + S_KH + col * 272u + ks * 32 + laneB272x4;
                    ldmB4(bh, kB); ldmB4(bl, kB + (S_KL - S_KH));
                    mma16(sS[0], qa, bh[0], bh[1]); mma16(sS[0], qa, bl[0], bl[1]); mma16(sS[0], ql, bh[0], bh[1]);
                    mma16(sS[1], qa, bh[2], bh[3]); mma16(sS[1], qa, bl[2], bl[3]); mma16(sS[1], ql, bh[2], bh[3]);
                }
                {
                    uint32_t bh[4], bl[4];
                    uint32_t mB = sb + S_MH + col * 272u + ks * 32 + laneB272x4;
                    ldmB4(bh, mB); ldmB4(bl, mB + (S_ML - S_MH));
                    mma16(sQ[0], qa, bh[0], bh[1]); mma16(sQ[0], qa, bl[0], bl[1]); mma16(sQ[0], ql, bh[0], bh[1]);
                    mma16(sQ[1], qa, bh[2], bh[3]); mma16(sQ[1], qa, bl[2], bl[3]); mma16(sQ[1], ql, bh[2], bh[3]);
                }
            }
        }
        // ---- A build (tiles with ct<=rt only) ----
        if (ct <= rt) {
            int t0 = rt * 16 + gid, t1 = t0 + 8;
            float g0 = Gs[t0], g1 = Gs[t1];
            #pragma unroll
            for (int j = 0; j < 2; j++) {
                int s0 = ct * 16 + 8 * j + 2 * tig, s1 = s0 + 1;
                float gs0 = Gs[s0], gs1 = Gs[s1], w0 = WSs[s0], w1 = WSs[s1];
                float a00 = (t0 >= s0) ? ex2n(g0 - gs0) * w0 * sS[j][0] : 0.f;
                float a01 = (t0 >= s1) ? ex2n(g0 - gs1) * w1 * sS[j][1] : 0.f;
                float a10 = (t1 >= s0) ? ex2n(g1 - gs0) * w0 * sS[j][2] : 0.f;
                float a11 = (t1 >= s1) ? ex2n(g1 - gs1) * w1 * sS[j][3] : 0.f;
                uint32_t hi, lo;
                sp2(a00, a01, hi, lo);
                uint32_t o = (uint32_t)t0 * 144u + (uint32_t)(s0 << 1);
                *(uint32_t*)(sm + S_AH + o) = hi; *(uint32_t*)(sm + S_AL + o) = lo;
                sp2(a10, a11, hi, lo);
                o = (uint32_t)t1 * 144u + (uint32_t)(s0 << 1);
                *(uint32_t*)(sm + S_AH + o) = hi; *(uint32_t*)(sm + S_AL + o) = lo;
            }
        }
        // ---- V^T split store (prefetched regs) [64n x 64s] ----
        #pragma unroll
        for (int ii = 0; ii < 8; ii++) {
            int i = tid + ii * NT;
            int s = i >> 6, n = i & 63;
            __nv_bfloat16 h, l; spl(vreg[ii], h, l);
            uint32_t o = (uint32_t)n * 144u + (uint32_t)(s << 1);
            *(__nv_bfloat16*)(sm + S_VH + o) = h;
            *(__nv_bfloat16*)(sm + S_VL + o) = l;
        }
        // ---- KT build: KT[m][s] = WG_s * k_s[m] ----
        for (int i = tid; i < 8192; i += NT) {
            int m = i >> 6, s = i & 63;
            uint32_t ko = (uint32_t)s * 272u + (uint32_t)(m << 1);
            float hv = __bfloat162float(*(__nv_bfloat16*)(sm + S_KH + ko));
            float lv = __bfloat162float(*(__nv_bfloat16*)(sm + S_KL + ko));
            __nv_bfloat16 h, l; spl((hv + lv) * WGs[s], h, l);
            uint32_t o = (uint32_t)m * 144u + (uint32_t)(s << 1);
            *(__nv_bfloat16*)(sm + S_TH + o) = h;
            *(__nv_bfloat16*)(sm + S_TL + o) = l;
        }
        __syncthreads();

        // ---- GEMM2: AV (ks<=rt) and dM = KT V ----
        float sA[2][4], sD[4][4];
        #pragma unroll
        for (int j = 0; j < 2; j++)
            #pragma unroll
            for (int e = 0; e < 4; e++) sA[j][e] = 0.f;
        #pragma unroll
        for (int j = 0; j < 4; j++)
            #pragma unroll
            for (int e = 0; e < 4; e++) sD[j][e] = 0.f;
        {
            const uint32_t ahB = sb + S_AH + (uint32_t)(rt * 16) * 144u + laneA144;
            #pragma unroll
            for (int ks = 0; ks < 4; ks++) {
                if (ks <= rt) {
                    uint32_t aa[4], al[4];
                    ldmA(aa, ahB + ks * 32); ldmA(al, ahB + (S_AL - S_AH) + ks * 32);
                    uint32_t bh[4], bl[4];
                    uint32_t vB = sb + S_VH + (uint32_t)(ct * 16) * 144u + ks * 32 + laneB144x4;
                    ldmB4(bh, vB); ldmB4(bl, vB + (S_VL - S_VH));
                    mma16(sA[0], aa, bh[0], bh[1]); mma16(sA[0], aa, bl[0], bl[1]); mma16(sA[0], al, bh[0], bh[1]);
                    mma16(sA[1], aa, bh[2], bh[3]); mma16(sA[1], aa, bl[2], bl[3]); mma16(sA[1], al, bh[2], bh[3]);
                }
            }
            const uint32_t ktB = sb + S_TH + (uint32_t)(wr * 16) * 144u + laneA144;
            #pragma unroll
            for (int ks = 0; ks < 4; ks++) {
                uint32_t ka[4], kl2[4];
                ldmA(ka, ktB + ks * 32); ldmA(kl2, ktB + (S_TL - S_TH) + ks * 32);
                #pragma unroll
                for (int jj = 0; jj < 2; jj++) {
                    uint32_t bh[4], bl[4];
                    uint32_t vB = sb + S_VH + (uint32_t)(wc * 32 + 16 * jj) * 144u + ks * 32 + laneB144x4;
                    ldmB4(bh, vB); ldmB4(bl, vB + (S_VL - S_VH));
                    mma16(sD[2*jj],   ka, bh[0], bh[1]); mma16(sD[2*jj],   ka, bl[0], bl[1]); mma16(sD[2*jj],   kl2, bh[0], bh[1]);
                    mma16(sD[2*jj+1], ka, bh[2], bh[3]); mma16(sD[2*jj+1], ka, bl[2], bl[3]); mma16(sD[2*jj+1], kl2, bh[2], bh[3]);
                }
            }
        }
        // ---- readout r = EG_t * QM0 + AV ----
        {
            int t0 = rt * 16 + gid, t1 = t0 + 8;
            float e0 = EGs[t0], e1 = EGs[t1];
            #pragma unroll
            for (int j = 0; j < 2; j++) {
                int n = ct * 16 + 8 * j + 2 * tig;
                float2 o0 = make_float2(fmaf(e0, sQ[j][0], sA[j][0]), fmaf(e0, sQ[j][1], sA[j][1]));
                float2 o1 = make_float2(fmaf(e1, sQ[j][2], sA[j][2]), fmaf(e1, sQ[j][3], sA[j][3]));
                *(float2*)(out + (tb0 + t0) * 128 + vh * 64 + n) = o0;
                *(float2*)(out + (tb0 + t1) * 128 + vh * 64 + n) = o1;
            }
        }
        // ---- M0 = s63 * M0 + dM ----
        {
            float s63 = *(float*)(sm + S_SC);
            int mr0 = wr * 16 + gid, mr1 = mr0 + 8;
            #pragma unroll
            for (int j = 0; j < 4; j++) {
                int n = wc * 32 + 8 * j + 2 * tig;
                float2* p0 = (float2*)(m0f + mr0 * 64 + n);
                float2* p1 = (float2*)(m0f + mr1 * 64 + n);
                float2 u0 = *p0, u1 = *p1;
                u0.x = fmaf(s63, u0.x, sD[j][0]); u0.y = fmaf(s63, u0.y, sD[j][1]);
                u1.x = fmaf(s63, u1.x, sD[j][2]); u1.y = fmaf(s63, u1.y, sD[j][3]);
                *p0 = u0; *p1 = u1;
            }
        }
        __syncthreads();
    }
}

extern "C" void kernel_launch(void* const* d_in, const int* in_sizes, int n_in,
                              void* d_out, int out_size)
{
    (void)in_sizes; (void)n_in; (void)out_size;
    cudaFuncSetAttribute(lmm_hmma, cudaFuncAttributeMaxDynamicSharedMemorySize, SMEMB);
    lmm_hmma<<<128, NT, SMEMB>>>((const float*)d_in[0], (const float*)d_in[1],
                                 (const float*)d_in[2], (const float*)d_in[3],
                                 (const float*)d_in[4], (const float*)d_in[5],
                                 (const float*)d_in[6], (float*)d_out);
}